// round 14
// baseline (speedup 1.0000x reference)
#include <cuda_runtime.h>
#include <math.h>

#define BATCH  2
#define NHEADS 16
#define BH     32
#define SQ     2048
#define SK     4096
#define DH     64
#define QT     64
#define KTILE  64
#define LS     68          // Q/K smem row stride (floats)
#define PS     72          // P smem row stride: banks 8ty+tx, conflict-free
#define VHS    36          // V half-row stride
#define QSCALE 0.1803368801111f   // 0.125 * log2(e)
// smem word offsets
#define QOFF   0
#define KOFF   4352                   // Q: 64*68
#define KBUF   4352                   // per K buffer
#define VOFF   (KOFF + 2*KBUF)        // 13056
#define VBUF   4640                   // two 64x36 halves + pad; half1 at +2308
#define VHALF  2308
#define POFF   (VOFF + 2*VBUF)        // 22336
#define SMWORDS (POFF + QT*PS)        // 26944 words = 107776 B

typedef unsigned long long ull;

__device__ __forceinline__ ull pk2(float lo, float hi) {
    ull r; asm("mov.b64 %0,{%1,%2};" : "=l"(r) : "f"(lo), "f"(hi)); return r;
}
__device__ __forceinline__ void upk2(ull v, float& lo, float& hi) {
    asm("mov.b64 {%0,%1},%2;" : "=f"(lo), "=f"(hi) : "l"(v));
}
__device__ __forceinline__ ull ffma2(ull a, ull b, ull c) {
    ull d; asm("fma.rn.f32x2 %0,%1,%2,%3;" : "=l"(d) : "l"(a), "l"(b), "l"(c)); return d;
}
__device__ __forceinline__ ull fmul2(ull a, ull b) {
    ull d; asm("mul.rn.f32x2 %0,%1,%2;" : "=l"(d) : "l"(a), "l"(b)); return d;
}
__device__ __forceinline__ void cpa16(unsigned int dst, const void* src) {
    asm volatile("cp.async.cg.shared.global [%0], [%1], 16;" :: "r"(dst), "l"(src));
}
// fast exp2 on the FMA pipe: |rel err| < 3e-6 for x in [-126, 126]
__device__ __forceinline__ float fexp2(float x) {
    float t = x + 12582912.0f;                // 1.5*2^23: low bits = rint(x)
    int   n = __float_as_int(t);
    float f = x - (t - 12582912.0f);          // f in [-0.5, 0.5]
    float p = 1.3333558e-3f;
    p = fmaf(p, f, 9.6181291e-3f);
    p = fmaf(p, f, 5.5504109e-2f);
    p = fmaf(p, f, 2.4022651e-1f);
    p = fmaf(p, f, 6.9314718e-1f);
    p = fmaf(p, f, 1.0f);
    return __int_as_float(__float_as_int(p) + (n << 23));
}

// ---------------- scratch ----------------
__device__ int   g_posq[BATCH * SQ];
__device__ float g_cosT[SK * 16];
__device__ float g_sinT[SK * 16];
__device__ float g_qr[BH * SQ * DH];
__device__ float g_kr[BH * SK * DH];

// ---------------- kernel 1: gather query positions -------------------------
__global__ void build_idx_kernel(const void* candA, const void* candB) {
    __shared__ int warp_sums[32];
    const int b   = blockIdx.x;
    const int tid = threadIdx.x;          // 1024 threads

    const int*   ai = (const int*)candA;  const float* af = (const float*)candA;
    const int*   bi = (const int*)candB;  const float* bf = (const float*)candB;
    bool a_is_pos = (ai[1] == 1 && ai[2] == 2 && ai[3] == 3 && ai[100] == 100) ||
                    (af[1] == 1.0f && af[2] == 2.0f && af[3] == 3.0f && af[100] == 100.0f);
    bool b_is_pos = (bi[1] == 1 && bi[2] == 2 && bi[3] == 3 && bi[100] == 100) ||
                    (bf[1] == 1.0f && bf[2] == 2.0f && bf[3] == 3.0f && bf[100] == 100.0f);
    const void* skipv = a_is_pos ? candB : (b_is_pos ? candA : candB);

    const unsigned int* sw = (const unsigned int*)skipv;
    bool w4 = true;
#pragma unroll
    for (int i = 0; i < 32; i++) {
        unsigned int x = sw[i];
        w4 = w4 && (x <= 1u || x == 0x3f800000u);
    }
    const unsigned char* s8  = (const unsigned char*)skipv;
    const unsigned int*  s32 = (const unsigned int*)skipv;

    g_posq[b * SQ + tid * 2]     = 0;
    g_posq[b * SQ + tid * 2 + 1] = 0;
    __syncthreads();

    const int base = tid * 4;
    int flags[4]; int c = 0;
#pragma unroll
    for (int u = 0; u < 4; u++) {
        int idx = b * SK + base + u;
        flags[u] = (w4 ? (s32[idx] != 0u) : (s8[idx] != 0)) ? 1 : 0;
        c += flags[u];
    }
    const int lane = tid & 31, warp = tid >> 5;
    int pre = c;
#pragma unroll
    for (int o = 1; o < 32; o <<= 1) {
        int t = __shfl_up_sync(0xffffffffu, pre, o);
        if (lane >= o) pre += t;
    }
    if (lane == 31) warp_sums[warp] = pre;
    __syncthreads();
    if (warp == 0) {
        int s = warp_sums[lane];
#pragma unroll
        for (int o = 1; o < 32; o <<= 1) {
            int t = __shfl_up_sync(0xffffffffu, s, o);
            if (lane >= o) s += t;
        }
        warp_sums[lane] = s;
    }
    __syncthreads();
    int offset = pre - c + (warp ? warp_sums[warp - 1] : 0);
#pragma unroll
    for (int u = 0; u < 4; u++) {
        if (flags[u] && offset < SQ)
            g_posq[b * SQ + offset] = base + u;
        offset += flags[u];
    }
}

// ---------------- kernel 2: cos/sin table ----------------------------------
__global__ void build_tab_kernel() {
    int i = blockIdx.x * blockDim.x + threadIdx.x;
    if (i >= SK * 16) return;
    int p = i >> 4, f = i & 15;
    float invf = (float)(1.0 / pow(10000.0, (double)(2 * f) / 32.0));
    float ang  = (float)p * invf;
    g_cosT[i] = cosf(ang);
    g_sinT[i] = sinf(ang);
}

// ---------------- kernel 3: RoPE on Q (scaled by 1/sqrt(D) * log2e) ---------
__global__ void rope_q_kernel(const float* __restrict__ q) {
    int t = blockIdx.x * blockDim.x + threadIdx.x;
    if (t >= BH * SQ * 32) return;
    int u   = t & 31;
    int row = t >> 5;
    int b   = row / (NHEADS * SQ);
    int r   = row & (SQ - 1);
    const float* x = q    + (size_t)row * DH;
    float*       y = g_qr + (size_t)row * DH;
    const float sc = QSCALE;
    if (u < 16) {
        int pos = g_posq[b * SQ + r];
        pos = min(max(pos, 0), SK - 1);
        float c  = g_cosT[pos * 16 + u];
        float s2 = g_sinT[pos * 16 + u];
        float x1 = x[u], x2 = x[u + 16];
        y[u]      = (x1 * c - x2 * s2) * sc;
        y[u + 16] = (x2 * c + x1 * s2) * sc;
    } else {
        int d = u + 16;
        y[d]      = x[d] * sc;
        y[d + 16] = x[d + 16] * sc;
    }
}

// ---------------- kernel 4: RoPE on K ---------------------------------------
__global__ void rope_k_kernel(const float* __restrict__ k) {
    int t = blockIdx.x * blockDim.x + threadIdx.x;
    if (t >= BH * SK * 32) return;
    int u   = t & 31;
    int row = t >> 5;
    int r   = row & (SK - 1);
    const float* x = k    + (size_t)row * DH;
    float*       y = g_kr + (size_t)row * DH;
    if (u < 16) {
        float c  = g_cosT[r * 16 + u];
        float s2 = g_sinT[r * 16 + u];
        float x1 = x[u], x2 = x[u + 16];
        y[u]      = x1 * c - x2 * s2;
        y[u + 16] = x2 * c + x1 * s2;
    } else {
        int d = u + 16;
        y[d]      = x[d];
        y[d + 16] = x[d + 16];
    }
}

// ---------------- kernel 5: flash attention ---------------------------------
// 128 threads, 64q x 64k tile, microtile 4q x 8k. No running max (log2-domain
// scores bounded); exp via FMA-pipe polynomial; l per-lane, reduced at end.
// Softmax(t-1) overlaps QK(t); cp.async double-buffered K/V; 1 barrier/tile.
__global__ __launch_bounds__(128, 2)
void attn_kernel(const float* __restrict__ v, float* __restrict__ out) {
    extern __shared__ float sm[];
    float* qs = sm + QOFF;
    float* ps = sm + POFF;

    const int bh  = blockIdx.y;
    const int qt  = (int)gridDim.x - 1 - (int)blockIdx.x;   // heavy-first
    const int b   = bh >> 4;
    const int q0  = qt * QT;
    const int tid = threadIdx.x;
    const int tx  = tid & 7;
    const int ty  = tid >> 3;            // 0..15

    const float* qr = g_qr + ((size_t)bh * SQ + q0) * DH;
    const float* kr = g_kr + (size_t)bh * SK * DH;
    const float* vp = v    + (size_t)bh * SK * DH;

    const int pmin = g_posq[b * SQ + q0];
    const int pmax = g_posq[b * SQ + q0 + QT - 1];
    const int nkt  = pmax / KTILE + 1;
    int p[4];
#pragma unroll
    for (int i = 0; i < 4; i++) p[i] = g_posq[b * SQ + q0 + ty + 16 * i];

    const unsigned int smbase = (unsigned int)__cvta_generic_to_shared(sm);
    const int cr = tid >> 1;             // row 0..63
    const int cc = (tid & 1) * 8;        // 8 chunks of 4 floats

    // prefetch K(0)
    {
        unsigned int kb = smbase + KOFF * 4;
        const float* krow = kr + (size_t)cr * DH;
#pragma unroll
        for (int u = 0; u < 8; u++) {
            int c = cc + u;
            cpa16(kb + (cr * LS + c * 4) * 4, krow + c * 4);
        }
        asm volatile("cp.async.commit_group;");
    }

    // load Q tile
#pragma unroll
    for (int i = 0; i < 8; i++) {
        int fid = tid + i * 128;
        int r = fid >> 4, c = (fid & 15) * 4;
        float4 f = *(const float4*)(qr + r * DH + c);
        *(float4*)(qs + r * LS + c) = f;
    }

    float l[4], sp[4][8];
    ull o2[4][4];
#pragma unroll
    for (int i = 0; i < 4; i++) {
        l[i] = 0.f;
#pragma unroll
        for (int j = 0; j < 4; j++) o2[i][j] = 0ULL;
    }

    const float* qrow[4];
#pragma unroll
    for (int i = 0; i < 4; i++) qrow[i] = qs + (ty + 16 * i) * LS;

#define ISSUE_K(T)                                                             \
    {                                                                          \
        unsigned int kb = smbase + (KOFF + ((T) & 1) * KBUF) * 4;              \
        const float* krow = kr + (size_t)((T) * KTILE + cr) * DH;              \
        _Pragma("unroll")                                                      \
        for (int u = 0; u < 8; u++) {                                          \
            int c = cc + u;                                                    \
            cpa16(kb + (cr * LS + c * 4) * 4, krow + c * 4);                   \
        }                                                                      \
    }
#define ISSUE_V(T)                                                             \
    {                                                                          \
        unsigned int vb = smbase + (VOFF + ((T) & 1) * VBUF) * 4;              \
        const float* vrow = vp + (size_t)((T) * KTILE + cr) * DH;              \
        _Pragma("unroll")                                                      \
        for (int u = 0; u < 8; u++) {                                          \
            int c = cc + u;                                                    \
            unsigned int vdst = (c < 8)                                        \
                ? vb + (cr * VHS + c * 4) * 4                                  \
                : vb + (VHALF + cr * VHS + (c - 8) * 4) * 4;                   \
            cpa16(vdst, vrow + c * 4);                                         \
        }                                                                      \
    }

#define QK_HALF(KS, KB)                                                        \
    _Pragma("unroll")                                                          \
    for (int kk = (KB); kk < (KB) + 32; kk += 4) {                             \
        ulonglong2 a4[4], b4[8];                                               \
        _Pragma("unroll")                                                      \
        for (int i = 0; i < 4; i++)                                            \
            a4[i] = *(const ulonglong2*)(qrow[i] + kk);                        \
        _Pragma("unroll")                                                      \
        for (int j = 0; j < 8; j++)                                            \
            b4[j] = *(const ulonglong2*)((KS) + (tx + 8 * j) * LS + kk);       \
        _Pragma("unroll")                                                      \
        for (int i = 0; i < 4; i++)                                            \
            _Pragma("unroll")                                                  \
            for (int j = 0; j < 8; j++) {                                      \
                s2[i][j] = ffma2(a4[i].x, b4[j].x, s2[i][j]);                  \
                s2[i][j] = ffma2(a4[i].y, b4[j].y, s2[i][j]);                  \
            }                                                                  \
    }

// exp each score on the FMA pipe, accumulate l per-lane, stage P.
#define SOFTMAX_PSTORE()                                                       \
    {                                                                          \
        _Pragma("unroll")                                                      \
        for (int i = 0; i < 4; i++) {                                          \
            float rs = 0.f;                                                    \
            _Pragma("unroll")                                                  \
            for (int j = 0; j < 8; j++) {                                      \
                sp[i][j] = fexp2(sp[i][j]);                                    \
                rs += sp[i][j];                                                \
            }                                                                  \
            l[i] += rs;                                                        \
            _Pragma("unroll")                                                  \
            for (int j = 0; j < 8; j++)                                        \
                ps[(ty + 16 * i) * PS + tx + 8 * j] = sp[i][j];                \
        }                                                                      \
    }

#define PV_ACC(VSB)                                                            \
    {                                                                          \
        const float* va = (VSB) + (tx < 4 ? tx * 8 : VHALF + (tx - 4) * 8);    \
        _Pragma("unroll")                                                      \
        for (int kk = 0; kk < KTILE; kk += 4) {                                \
            float4 pa4[4];                                                     \
            _Pragma("unroll")                                                  \
            for (int i = 0; i < 4; i++)                                        \
                pa4[i] = *(const float4*)(ps + (ty + 16 * i) * PS + kk);       \
            _Pragma("unroll")                                                  \
            for (int u = 0; u < 4; u++) {                                      \
                const float* vr = va + (kk + u) * VHS;                         \
                ulonglong2 vv = *(const ulonglong2*)(vr);                      \
                ulonglong2 vw = *(const ulonglong2*)(vr + 4);                  \
                _Pragma("unroll")                                              \
                for (int i = 0; i < 4; i++) {                                  \
                    float pvv = ((const float*)&pa4[i])[u];                    \
                    ull pr = pk2(pvv, pvv);                                    \
                    o2[i][0] = ffma2(pr, vv.x, o2[i][0]);                      \
                    o2[i][1] = ffma2(pr, vv.y, o2[i][1]);                      \
                    o2[i][2] = ffma2(pr, vw.x, o2[i][2]);                      \
                    o2[i][3] = ffma2(pr, vw.y, o2[i][3]);                      \
                }                                                              \
            }                                                                  \
        }                                                                      \
    }

// fold packed halves + causal mask (masked -> -126: fexp2 gives ~0)
#define FOLD_MASK(K0)                                                          \
    {                                                                          \
        _Pragma("unroll")                                                      \
        for (int i = 0; i < 4; i++)                                            \
            _Pragma("unroll")                                                  \
            for (int j = 0; j < 8; j++) {                                      \
                float lo, hi; upk2(s2[i][j], lo, hi);                          \
                sp[i][j] = lo + hi;                                            \
            }                                                                  \
        if ((K0) + KTILE - 1 > pmin) {                                         \
            _Pragma("unroll")                                                  \
            for (int i = 0; i < 4; i++)                                        \
                _Pragma("unroll")                                              \
                for (int j = 0; j < 8; j++)                                    \
                    if ((K0) + tx + 8 * j > p[i]) sp[i][j] = -126.0f;          \
        }                                                                      \
    }

    // ---- peel t = 0 : QK only ----
    {
        asm volatile("cp.async.wait_group 0;");
        __syncthreads();
        if (1 < nkt) ISSUE_K(1);
        ISSUE_V(0);
        asm volatile("cp.async.commit_group;");

        ull s2[4][8];
#pragma unroll
        for (int i = 0; i < 4; i++)
#pragma unroll
            for (int j = 0; j < 8; j++) s2[i][j] = 0ULL;
        const float* ks = sm + KOFF;
        QK_HALF(ks, 0);
        QK_HALF(ks, 32);
        FOLD_MASK(0);
    }

    // ---- main pipelined loop ----
    for (int t = 1; t < nkt; t++) {
        const float* ks    = sm + KOFF + (t & 1) * KBUF;
        const float* vprev = sm + VOFF + ((t - 1) & 1) * VBUF;

        asm volatile("cp.async.wait_group 0;");
        __syncthreads();
        if (t + 1 < nkt) ISSUE_K(t + 1);
        ISSUE_V(t);
        asm volatile("cp.async.commit_group;");

        ull s2[4][8];
#pragma unroll
        for (int i = 0; i < 4; i++)
#pragma unroll
            for (int j = 0; j < 8; j++) s2[i][j] = 0ULL;

        // QK part 1 + softmax(t-1): independent chains
        QK_HALF(ks, 0);
        SOFTMAX_PSTORE();
        __syncwarp();
        QK_HALF(ks, 32);
        PV_ACC(vprev);
        FOLD_MASK(t * KTILE);
    }

    // ---- tail: softmax + PV of last tile ----
    asm volatile("cp.async.wait_group 0;");
    __syncthreads();
    SOFTMAX_PSTORE();
    __syncwarp();
    {
        const float* vlast = sm + VOFF + ((nkt - 1) & 1) * VBUF;
        PV_ACC(vlast);
    }

    // epilogue: reduce l across the 8-lane row group, normalize, store
#pragma unroll
    for (int i = 0; i < 4; i++) {
        float lt = l[i];
        lt += __shfl_xor_sync(0xffffffffu, lt, 1);
        lt += __shfl_xor_sync(0xffffffffu, lt, 2);
        lt += __shfl_xor_sync(0xffffffffu, lt, 4);
        float inv = 1.0f / lt;
        ull iv = pk2(inv, inv);
        ulonglong2 w0, w1;
        w0.x = fmul2(o2[i][0], iv); w0.y = fmul2(o2[i][1], iv);
        w1.x = fmul2(o2[i][2], iv); w1.y = fmul2(o2[i][3], iv);
        float* orow = out + ((size_t)bh * SQ + q0 + ty + 16 * i) * DH + tx * 8;
        *(ulonglong2*)orow       = w0;
        *(ulonglong2*)(orow + 4) = w1;
    }
}

// ---------------- launch ------------------------------------------------------
extern "C" void kernel_launch(void* const* d_in, const int* in_sizes, int n_in,
                              void* d_out, int out_size) {
    const float* q = nullptr; const float* k = nullptr; const float* v = nullptr;
    const void* cand[2] = {nullptr, nullptr}; int nc = 0;
    for (int i = 0; i < n_in; i++) {
        long long sz = in_sizes[i];
        if (sz == 4194304) { q = (const float*)d_in[i]; }
        else if (sz == 8388608) { if (!k) k = (const float*)d_in[i]; else v = (const float*)d_in[i]; }
        else if (sz == 8192) { if (nc < 2) cand[nc++] = d_in[i]; }
    }
    if (nc == 1) cand[1] = cand[0];
    if (!q || !k || !v || nc == 0) {
        q = (const float*)d_in[0]; k = (const float*)d_in[1]; v = (const float*)d_in[2];
        cand[0] = d_in[4]; cand[1] = d_in[5];
    }
    float* out = (float*)d_out;

    build_idx_kernel<<<BATCH, 1024>>>(cand[0], cand[1]);
    build_tab_kernel<<<(SK * 16 + 255) / 256, 256>>>();
    rope_q_kernel<<<(BH * SQ * 32 + 255) / 256, 256>>>(q);
    rope_k_kernel<<<(BH * SK * 32 + 255) / 256, 256>>>(k);

    const int smem_bytes = SMWORDS * (int)sizeof(float);   // 107776
    cudaFuncSetAttribute(attn_kernel,
                         cudaFuncAttributeMaxDynamicSharedMemorySize, smem_bytes);
    dim3 grid(SQ / QT, BH);
    attn_kernel<<<grid, 128, smem_bytes>>>(v, out);
}

// round 15
// speedup vs baseline: 4.0320x; 4.0320x over previous
#include <cuda_runtime.h>
#include <cuda_fp16.h>
#include <math.h>
#include <stdint.h>

#define BATCH  2
#define NHEADS 16
#define BH     32
#define SQ     2048
#define SK     4096
#define DH     64
#define QT     64          // q rows per CTA (4 warps x 16)
#define KT     64          // k tile
#define SH     72          // smem stride in halfs (144B rows, LDSM conflict-free)
#define QSCALE 0.1803368801111f   // 0.125 * log2(e)

// smem half offsets
#define HQ     0
#define HK0    4608               // 64*72
#define HV0    9216
#define HKVSTR 9216               // buffer stride (K1 = HK0+HKVSTR, V1 = HV0+HKVSTR)
#define SMHALF 23040              // 46080 bytes

__device__ __forceinline__ float fexp2(float x) {
    float t = x + 12582912.0f;
    int   n = __float_as_int(t);
    float f = x - (t - 12582912.0f);
    float p = 1.3333558e-3f;
    p = fmaf(p, f, 9.6181291e-3f);
    p = fmaf(p, f, 5.5504109e-2f);
    p = fmaf(p, f, 2.4022651e-1f);
    p = fmaf(p, f, 6.9314718e-1f);
    p = fmaf(p, f, 1.0f);
    return __int_as_float(__float_as_int(p) + (n << 23));
}
__device__ __forceinline__ void cpa16(uint32_t dst, const void* src) {
    asm volatile("cp.async.cg.shared.global [%0], [%1], 16;" :: "r"(dst), "l"(src));
}
__device__ __forceinline__ void ldsm4(uint32_t& r0, uint32_t& r1, uint32_t& r2,
                                      uint32_t& r3, uint32_t a) {
    asm volatile("ldmatrix.sync.aligned.m8n8.x4.shared.b16 {%0,%1,%2,%3},[%4];"
                 : "=r"(r0), "=r"(r1), "=r"(r2), "=r"(r3) : "r"(a));
}
__device__ __forceinline__ void ldsm4t(uint32_t& r0, uint32_t& r1, uint32_t& r2,
                                       uint32_t& r3, uint32_t a) {
    asm volatile("ldmatrix.sync.aligned.m8n8.x4.trans.shared.b16 {%0,%1,%2,%3},[%4];"
                 : "=r"(r0), "=r"(r1), "=r"(r2), "=r"(r3) : "r"(a));
}
__device__ __forceinline__ void hmma(float* c, uint32_t a0, uint32_t a1, uint32_t a2,
                                     uint32_t a3, uint32_t b0, uint32_t b1) {
    asm volatile(
        "mma.sync.aligned.m16n8k16.row.col.f32.f16.f16.f32 "
        "{%0,%1,%2,%3},{%4,%5,%6,%7},{%8,%9},{%0,%1,%2,%3};"
        : "+f"(c[0]), "+f"(c[1]), "+f"(c[2]), "+f"(c[3])
        : "r"(a0), "r"(a1), "r"(a2), "r"(a3), "r"(b0), "r"(b1));
}
__device__ __forceinline__ uint32_t packh2(float lo, float hi) {
    __half2 h = __floats2half2_rn(lo, hi);
    return *(uint32_t*)&h;
}

// ---------------- scratch ----------------
__device__ int    g_posq[BATCH * SQ];
__device__ float  g_cosT[SK * 16];
__device__ float  g_sinT[SK * 16];
__device__ __half g_qh[BH * SQ * DH];
__device__ __half g_kh[BH * SK * DH];
__device__ __half g_vh[BH * SK * DH];

// ---------------- kernel 1: gather query positions --------------------------
__global__ void build_idx_kernel(const void* candA, const void* candB) {
    __shared__ int warp_sums[32];
    const int b = blockIdx.x, tid = threadIdx.x;
    const int* ai = (const int*)candA; const float* af = (const float*)candA;
    const int* bi = (const int*)candB; const float* bf = (const float*)candB;
    bool a_is_pos = (ai[1] == 1 && ai[2] == 2 && ai[3] == 3 && ai[100] == 100) ||
                    (af[1] == 1.0f && af[2] == 2.0f && af[3] == 3.0f && af[100] == 100.0f);
    bool b_is_pos = (bi[1] == 1 && bi[2] == 2 && bi[3] == 3 && bi[100] == 100) ||
                    (bf[1] == 1.0f && bf[2] == 2.0f && bf[3] == 3.0f && bf[100] == 100.0f);
    const void* skipv = a_is_pos ? candB : (b_is_pos ? candA : candB);
    const unsigned int* sw = (const unsigned int*)skipv;
    bool w4 = true;
#pragma unroll
    for (int i = 0; i < 32; i++) {
        unsigned int x = sw[i];
        w4 = w4 && (x <= 1u || x == 0x3f800000u);
    }
    const unsigned char* s8 = (const unsigned char*)skipv;
    const unsigned int* s32 = (const unsigned int*)skipv;
    g_posq[b * SQ + tid * 2] = 0;
    g_posq[b * SQ + tid * 2 + 1] = 0;
    __syncthreads();
    const int base = tid * 4;
    int flags[4], c = 0;
#pragma unroll
    for (int u = 0; u < 4; u++) {
        int idx = b * SK + base + u;
        flags[u] = (w4 ? (s32[idx] != 0u) : (s8[idx] != 0)) ? 1 : 0;
        c += flags[u];
    }
    const int lane = tid & 31, warp = tid >> 5;
    int pre = c;
#pragma unroll
    for (int o = 1; o < 32; o <<= 1) {
        int t = __shfl_up_sync(0xffffffffu, pre, o);
        if (lane >= o) pre += t;
    }
    if (lane == 31) warp_sums[warp] = pre;
    __syncthreads();
    if (warp == 0) {
        int s = warp_sums[lane];
#pragma unroll
        for (int o = 1; o < 32; o <<= 1) {
            int t = __shfl_up_sync(0xffffffffu, s, o);
            if (lane >= o) s += t;
        }
        warp_sums[lane] = s;
    }
    __syncthreads();
    int offset = pre - c + (warp ? warp_sums[warp - 1] : 0);
#pragma unroll
    for (int u = 0; u < 4; u++) {
        if (flags[u] && offset < SQ) g_posq[b * SQ + offset] = base + u;
        offset += flags[u];
    }
}

// ---------------- kernel 2: cos/sin table ------------------------------------
__global__ void build_tab_kernel() {
    int i = blockIdx.x * blockDim.x + threadIdx.x;
    if (i >= SK * 16) return;
    int p = i >> 4, f = i & 15;
    float invf = (float)(1.0 / pow(10000.0, (double)(2 * f) / 32.0));
    g_cosT[i] = cosf((float)p * invf);
    g_sinT[i] = sinf((float)p * invf);
}

// ---------------- kernel 3: RoPE Q -> fp16 (scaled) ---------------------------
__global__ void rope_q_kernel(const float* __restrict__ q) {
    int t = blockIdx.x * blockDim.x + threadIdx.x;
    if (t >= BH * SQ * 32) return;
    int u = t & 31, row = t >> 5;
    int b = row / (NHEADS * SQ), r = row & (SQ - 1);
    const float* x = q + (size_t)row * DH;
    __half* y = g_qh + (size_t)row * DH;
    if (u < 16) {
        int pos = min(max(g_posq[b * SQ + r], 0), SK - 1);
        float c = g_cosT[pos * 16 + u], s2 = g_sinT[pos * 16 + u];
        float x1 = x[u], x2 = x[u + 16];
        y[u]      = __float2half_rn((x1 * c - x2 * s2) * QSCALE);
        y[u + 16] = __float2half_rn((x2 * c + x1 * s2) * QSCALE);
    } else {
        int d = u + 16;
        y[d]      = __float2half_rn(x[d] * QSCALE);
        y[d + 16] = __float2half_rn(x[d + 16] * QSCALE);
    }
}

// ---------------- kernel 4: RoPE K -> fp16 ------------------------------------
__global__ void rope_k_kernel(const float* __restrict__ k) {
    int t = blockIdx.x * blockDim.x + threadIdx.x;
    if (t >= BH * SK * 32) return;
    int u = t & 31, row = t >> 5, r = row & (SK - 1);
    const float* x = k + (size_t)row * DH;
    __half* y = g_kh + (size_t)row * DH;
    if (u < 16) {
        float c = g_cosT[r * 16 + u], s2 = g_sinT[r * 16 + u];
        float x1 = x[u], x2 = x[u + 16];
        y[u]      = __float2half_rn(x1 * c - x2 * s2);
        y[u + 16] = __float2half_rn(x2 * c + x1 * s2);
    } else {
        int d = u + 16;
        y[d]      = __float2half_rn(x[d]);
        y[d + 16] = __float2half_rn(x[d + 16]);
    }
}

// ---------------- kernel 5: V -> fp16 -----------------------------------------
__global__ void vhalf_kernel(const float* __restrict__ v) {
    int i = blockIdx.x * blockDim.x + threadIdx.x;
    int n8 = BH * SK * DH / 8;
    if (i >= n8) return;
    float4 f0 = ((const float4*)v)[i * 2];
    float4 f1 = ((const float4*)v)[i * 2 + 1];
    uint32_t h[4];
    h[0] = packh2(f0.x, f0.y); h[1] = packh2(f0.z, f0.w);
    h[2] = packh2(f1.x, f1.y); h[3] = packh2(f1.z, f1.w);
    ((uint4*)g_vh)[i] = *(uint4*)h;
}

// ---------------- kernel 6: fp16 mma.sync flash attention ---------------------
// 128 threads (4 warps). q-tile 64 (16 rows/warp), k-tile 64. All operands fp16,
// fp32 accum. P stays in registers (C-frag -> A-frag relayout). No running max;
// exp on FMA pipe; l per-thread, quad-reduced at end. 1 barrier/tile.
__global__ __launch_bounds__(128, 2)
void attn_kernel(float* __restrict__ out) {
    extern __shared__ __align__(16) char smc[];
    __half* smh = (__half*)smc;
    const uint32_t smb = (uint32_t)__cvta_generic_to_shared(smc);

    const int tid = threadIdx.x;
    const int w = tid >> 5, l = tid & 31;
    const int bh = blockIdx.y;
    const int qt = (int)gridDim.x - 1 - (int)blockIdx.x;   // heavy-first
    const int b = bh >> 4;
    const int q0 = qt * QT;

    const __half* khb = g_kh + (size_t)bh * SK * DH;
    const __half* vhb = g_vh + (size_t)bh * SK * DH;

    const int pmin = g_posq[b * SQ + q0];
    const int pmax = g_posq[b * SQ + q0 + QT - 1];
    const int nkt  = pmax / KT + 1;

    const int r0g = q0 + 16 * w + (l >> 2);       // this thread's row 0 (global)
    const int p0 = g_posq[b * SQ + r0g];
    const int p1 = g_posq[b * SQ + r0g + 8];

    // ldmatrix lane-address components
    const int qr_l = (l & 7) + 8 * ((l >> 3) & 1);
    const int qc_l = 8 * (l >> 4);
    const int kr_l = (l & 7) + 8 * (l >> 4);
    const int kc_l = 8 * ((l >> 3) & 1);

    // cp.async loader: K/V rows 64 x 64 halfs; thread: row tid>>1, 4 chunks each
    const int cr = tid >> 1;
    const int cc = (tid & 1) * 4;
#define ISSUE_KV(T)                                                            \
    {                                                                          \
        int buf_ = (T) & 1;                                                    \
        uint32_t kdst = smb + (HK0 + buf_ * HKVSTR + cr * SH) * 2;             \
        uint32_t vdst = smb + (HV0 + buf_ * HKVSTR + cr * SH) * 2;             \
        const __half* ks_ = khb + (size_t)((T) * KT + cr) * DH;                \
        const __half* vs_ = vhb + (size_t)((T) * KT + cr) * DH;                \
        _Pragma("unroll")                                                      \
        for (int u = 0; u < 4; u++) {                                          \
            int c = (cc + u) * 8;                                              \
            cpa16(kdst + c * 2, ks_ + c);                                      \
            cpa16(vdst + c * 2, vs_ + c);                                      \
        }                                                                      \
        asm volatile("cp.async.commit_group;");                                \
    }

    ISSUE_KV(0);

    // stage Q (64 x 64 halfs, stride SH)
    {
        const __half* qh = g_qh + ((size_t)bh * SQ + q0) * DH;
#pragma unroll
        for (int u = 0; u < 4; u++) {
            int c = (cc + u) * 8;
            *(uint4*)(smh + HQ + cr * SH + c) = *(const uint4*)(qh + (size_t)cr * DH + c);
        }
    }
    __syncthreads();

    // preload Q A-frags (tile-invariant): 4 k-blocks
    uint32_t qa[4][4];
#pragma unroll
    for (int kb = 0; kb < 4; kb++) {
        uint32_t a = smb + ((HQ + (16 * w + qr_l) * SH + 16 * kb + qc_l)) * 2;
        ldsm4(qa[kb][0], qa[kb][1], qa[kb][2], qa[kb][3], a);
    }

    float o[8][4];
#pragma unroll
    for (int nb = 0; nb < 8; nb++)
#pragma unroll
        for (int j = 0; j < 4; j++) o[nb][j] = 0.f;
    float l0 = 0.f, l1 = 0.f;

    for (int t = 0; t < nkt; t++) {
        const int buf = t & 1;
        const int k0 = t * KT;
        const uint32_t kbh = HK0 + buf * HKVSTR;
        const uint32_t vbh = HV0 + buf * HKVSTR;

        asm volatile("cp.async.wait_group 0;");
        __syncthreads();
        if (t + 1 < nkt) ISSUE_KV(t + 1);

        // ---- S = Q K^T ----
        float s[8][4];
#pragma unroll
        for (int nb = 0; nb < 8; nb++)
#pragma unroll
            for (int j = 0; j < 4; j++) s[nb][j] = 0.f;
#pragma unroll
        for (int kb = 0; kb < 4; kb++) {
#pragma unroll
            for (int nbp = 0; nbp < 4; nbp++) {
                uint32_t b0, b1, b2, b3;
                uint32_t a = smb + ((kbh + (16 * nbp + kr_l) * SH + 16 * kb + kc_l)) * 2;
                ldsm4(b0, b1, b2, b3, a);
                hmma(s[2 * nbp],     qa[kb][0], qa[kb][1], qa[kb][2], qa[kb][3], b0, b1);
                hmma(s[2 * nbp + 1], qa[kb][0], qa[kb][1], qa[kb][2], qa[kb][3], b2, b3);
            }
        }

        // ---- softmax in registers (exp on FMA pipe, mask, pack to fp16) ----
        const bool fulltile = (k0 + KT - 1 <= pmin);
#pragma unroll
        for (int nb = 0; nb < 8; nb++) {
            int kc = k0 + 8 * nb + 2 * (l & 3);
            float e0 = fexp2(s[nb][0]);
            float e1 = fexp2(s[nb][1]);
            float e2 = fexp2(s[nb][2]);
            float e3 = fexp2(s[nb][3]);
            if (!fulltile) {
                if (kc     > p0) e0 = 0.f;
                if (kc + 1 > p0) e1 = 0.f;
                if (kc     > p1) e2 = 0.f;
                if (kc + 1 > p1) e3 = 0.f;
            }
            l0 += e0 + e1;
            l1 += e2 + e3;
            s[nb][0] = e0; s[nb][1] = e1; s[nb][2] = e2; s[nb][3] = e3;
        }
        uint32_t pa[4][4];
#pragma unroll
        for (int kb = 0; kb < 4; kb++) {
            pa[kb][0] = packh2(s[2 * kb][0],     s[2 * kb][1]);
            pa[kb][1] = packh2(s[2 * kb][2],     s[2 * kb][3]);
            pa[kb][2] = packh2(s[2 * kb + 1][0], s[2 * kb + 1][1]);
            pa[kb][3] = packh2(s[2 * kb + 1][2], s[2 * kb + 1][3]);
        }

        // ---- O += P V ----
#pragma unroll
        for (int kb = 0; kb < 4; kb++) {
#pragma unroll
            for (int nbp = 0; nbp < 4; nbp++) {
                uint32_t b0, b1, b2, b3;
                uint32_t a = smb + ((vbh + (16 * kb + qr_l) * SH + 16 * nbp + qc_l)) * 2;
                ldsm4t(b0, b1, b2, b3, a);
                hmma(o[2 * nbp],     pa[kb][0], pa[kb][1], pa[kb][2], pa[kb][3], b0, b1);
                hmma(o[2 * nbp + 1], pa[kb][0], pa[kb][1], pa[kb][2], pa[kb][3], b2, b3);
            }
        }
    }

    // ---- epilogue: quad-reduce l, normalize, store ----
    l0 += __shfl_xor_sync(0xffffffffu, l0, 1);
    l0 += __shfl_xor_sync(0xffffffffu, l0, 2);
    l1 += __shfl_xor_sync(0xffffffffu, l1, 1);
    l1 += __shfl_xor_sync(0xffffffffu, l1, 2);
    float inv0 = 1.0f / l0, inv1 = 1.0f / l1;
    float* o0p = out + ((size_t)bh * SQ + r0g) * DH + 2 * (l & 3);
    float* o1p = o0p + 8 * DH;
#pragma unroll
    for (int nb = 0; nb < 8; nb++) {
        float2 w0 = make_float2(o[nb][0] * inv0, o[nb][1] * inv0);
        float2 w1 = make_float2(o[nb][2] * inv1, o[nb][3] * inv1);
        *(float2*)(o0p + 8 * nb) = w0;
        *(float2*)(o1p + 8 * nb) = w1;
    }
}

// ---------------- launch --------------------------------------------------------
extern "C" void kernel_launch(void* const* d_in, const int* in_sizes, int n_in,
                              void* d_out, int out_size) {
    const float* q = nullptr; const float* k = nullptr; const float* v = nullptr;
    const void* cand[2] = {nullptr, nullptr}; int nc = 0;
    for (int i = 0; i < n_in; i++) {
        long long sz = in_sizes[i];
        if (sz == 4194304) { q = (const float*)d_in[i]; }
        else if (sz == 8388608) { if (!k) k = (const float*)d_in[i]; else v = (const float*)d_in[i]; }
        else if (sz == 8192) { if (nc < 2) cand[nc++] = d_in[i]; }
    }
    if (nc == 1) cand[1] = cand[0];
    if (!q || !k || !v || nc == 0) {
        q = (const float*)d_in[0]; k = (const float*)d_in[1]; v = (const float*)d_in[2];
        cand[0] = d_in[4]; cand[1] = d_in[5];
    }
    float* out = (float*)d_out;

    build_idx_kernel<<<BATCH, 1024>>>(cand[0], cand[1]);
    build_tab_kernel<<<(SK * 16 + 255) / 256, 256>>>();
    rope_q_kernel<<<(BH * SQ * 32 + 255) / 256, 256>>>(q);
    rope_k_kernel<<<(BH * SK * 32 + 255) / 256, 256>>>(k);
    vhalf_kernel<<<(BH * SK * DH / 8 + 255) / 256, 256>>>(v);

    const int smem_bytes = SMHALF * 2;   // 46080
    cudaFuncSetAttribute(attn_kernel,
                         cudaFuncAttributeMaxDynamicSharedMemorySize, smem_bytes);
    dim3 grid(SQ / QT, BH);
    attn_kernel<<<grid, 128, smem_bytes>>>(out);
}